// round 2
// baseline (speedup 1.0000x reference)
#include <cuda_runtime.h>
#include <cuda_bf16.h>
#include <cstdint>

#define Bsz 8
#define Dm  4096
#define D3  12288
#define Ssz 16
#define FFm 16384

typedef unsigned long long u64;

// ---------------- scratch (allocation-free: __device__ globals) ----------------
__device__ float g_xn  [Bsz * Dm];   // rmsnorm(x)
__device__ float g_z   [Bsz * D3];   // xn @ proj_w   (atomic accum)
__device__ float g_x2  [Bsz * Dm];   // gate channel
__device__ float g_x1v [Bsz * Dm];   // x1*v
__device__ float g_y   [Bsz * Dm];   // gated output
__device__ float g_xout[Bsz * Dm];   // y@out_w + out_b + x (atomic accum)
__device__ float g_xn2 [Bsz * Dm];   // rmsnorm(xout)
__device__ float g_g1  [Bsz * FFm];  // xn2 @ mlp_w1  (atomic accum)
__device__ float g_g3  [Bsz * FFm];  // xn2 @ mlp_w3  (atomic accum)
__device__ float g_h   [Bsz * FFm];  // silu(g1)*g3

// ---------------- packed f32x2 helpers ----------------
__device__ __forceinline__ u64 pack2(float lo, float hi) {
    u64 r;
    asm("mov.b64 %0, {%1, %2};" : "=l"(r) : "r"(__float_as_uint(lo)), "r"(__float_as_uint(hi)));
    return r;
}
__device__ __forceinline__ void unpack2(u64 v, float& lo, float& hi) {
    unsigned ulo, uhi;
    asm("mov.b64 {%0, %1}, %2;" : "=r"(ulo), "=r"(uhi) : "l"(v));
    lo = __uint_as_float(ulo); hi = __uint_as_float(uhi);
}

// ---------------- batched (B=8) split-K GEMV, float4 weight loads ----------------
// W: [K, N] row-major. out[b,n] += sum_k xin[b,k]*W[k,n]
// 256 threads; thread owns 4 consecutive columns (LDG.128). Block covers 1024 cols.
// grid = (N/1024, K/KCHUNK). smem holds x duplicated as (xb,xb) u64 pairs.
template<int KCHUNK>
__device__ __forceinline__ void gemv4_body(const float* __restrict__ W,
                                           const float* __restrict__ xin,
                                           float* __restrict__ out,
                                           int K, int N) {
    __shared__ __align__(16) u64 xs2[KCHUNK * 8];   // xs2[k*8 + b] = (x[b,k0+k], x[b,k0+k])
    const int n0 = (blockIdx.x * 256 + threadIdx.x) * 4;
    const int k0 = blockIdx.y * KCHUNK;

    for (int t = threadIdx.x; t < KCHUNK * 8; t += 256) {
        int b = t / KCHUNK, k = t - b * KCHUNK;       // consecutive t -> consecutive k (coalesced)
        float v = xin[b * K + k0 + k];
        xs2[k * 8 + b] = pack2(v, v);
    }
    __syncthreads();

    u64 acc01[8], acc23[8];
#pragma unroll
    for (int b = 0; b < 8; b++) { acc01[b] = pack2(0.f, 0.f); acc23[b] = pack2(0.f, 0.f); }

    const float4* Wp = reinterpret_cast<const float4*>(W + (size_t)k0 * N + n0);
    const size_t strd = (size_t)(N >> 2);
#pragma unroll 4
    for (int k = 0; k < KCHUNK; k++) {
        float4 w = Wp[(size_t)k * strd];
        u64 w01 = pack2(w.x, w.y);
        u64 w23 = pack2(w.z, w.w);
        const u64* xp = xs2 + k * 8;
#pragma unroll
        for (int b = 0; b < 8; b++) {
            u64 xb = xp[b];
            asm("fma.rn.f32x2 %0, %1, %2, %0;" : "+l"(acc01[b]) : "l"(w01), "l"(xb));
            asm("fma.rn.f32x2 %0, %1, %2, %0;" : "+l"(acc23[b]) : "l"(w23), "l"(xb));
        }
    }

#pragma unroll
    for (int b = 0; b < 8; b++) {
        float a0, a1, a2, a3;
        unpack2(acc01[b], a0, a1);
        unpack2(acc23[b], a2, a3);
        float* ob = out + (size_t)b * N + n0;
        atomicAdd(ob + 0, a0);
        atomicAdd(ob + 1, a1);
        atomicAdd(ob + 2, a2);
        atomicAdd(ob + 3, a3);
    }
}

__global__ void __launch_bounds__(256) k_gemv_proj(const float* __restrict__ W) { gemv4_body<128>(W, g_xn,  g_z,    Dm,  D3);  }
__global__ void __launch_bounds__(256) k_gemv_out (const float* __restrict__ W) { gemv4_body<64> (W, g_y,   g_xout, Dm,  Dm);  }
__global__ void __launch_bounds__(256) k_gemv_w1  (const float* __restrict__ W) { gemv4_body<128>(W, g_xn2, g_g1,   Dm,  FFm); }
__global__ void __launch_bounds__(256) k_gemv_w3  (const float* __restrict__ W) { gemv4_body<128>(W, g_xn2, g_g3,   Dm,  FFm); }
__global__ void __launch_bounds__(256) k_gemv_w2  (const float* __restrict__ W, float* __restrict__ out_x) {
    gemv4_body<128>(W, g_h, out_x, FFm, Dm);
}

// ---------------- rmsnorm ----------------
__device__ __forceinline__ void rmsnorm_body(const float* __restrict__ xr,
                                             const float* __restrict__ w,
                                             float* __restrict__ xo) {
    float ss = 0.f;
    for (int i = threadIdx.x; i < Dm; i += blockDim.x) { float v = xr[i]; ss += v * v; }
#pragma unroll
    for (int o = 16; o; o >>= 1) ss += __shfl_xor_sync(0xffffffffu, ss, o);
    __shared__ float red[32];
    int wid = threadIdx.x >> 5, lane = threadIdx.x & 31;
    if (lane == 0) red[wid] = ss;
    __syncthreads();
    int nw = blockDim.x >> 5;
    if (wid == 0) {
        float t = (lane < nw) ? red[lane] : 0.f;
#pragma unroll
        for (int o = 16; o; o >>= 1) t += __shfl_xor_sync(0xffffffffu, t, o);
        if (lane == 0) red[0] = t;
    }
    __syncthreads();
    float scale = rsqrtf(red[0] * (1.f / Dm) + 1e-6f);
    for (int i = threadIdx.x; i < Dm; i += blockDim.x) xo[i] = xr[i] * scale * w[i];
}

__global__ void k_rmsnorm_pre(const float* __restrict__ x, const float* __restrict__ w) {
    int b = blockIdx.x;
    rmsnorm_body(x + b * Dm, w, g_xn + b * Dm);
}
__global__ void k_rmsnorm_post(const float* __restrict__ w) {
    int b = blockIdx.x;
    rmsnorm_body(g_xout + b * Dm, w, g_xn2 + b * Dm);
}

// ---------------- init: zero atomic accumulators, seed xout = x + out_b ----------------
__global__ void k_init(const float* __restrict__ x, const float* __restrict__ out_b) {
    int i = blockIdx.x * blockDim.x + threadIdx.x;      // 131072 threads
    if (i < Bsz * D3)  g_z[i] = 0.f;
    if (i < Bsz * FFm) { g_g1[i] = 0.f; g_g3[i] = 0.f; }
    if (i < Bsz * Dm)  g_xout[i] = x[i] + out_b[i & (Dm - 1)];
}

// ---------------- FIR taps: one thread per (b, d), 3 channels ----------------
__global__ void k_fir(const float* __restrict__ fir_state,
                      const float* __restrict__ sf_weight,
                      const float* __restrict__ sf_bias,
                      float* __restrict__ out_fir) {
    int idx = blockIdx.x * blockDim.x + threadIdx.x;   // [0, 32768)
    int b = idx >> 12;
    int d = idx & (Dm - 1);
    int head = d >> 7;
    int i    = d & 127;
    int base = head * 384 + i;

    float zp[3];
#pragma unroll
    for (int j = 0; j < 3; j++) {
        int n3 = base + j * 128;
        float u  = g_z[b * D3 + n3];
        float f0 = fir_state[(b * D3 + n3) * 2 + 0];
        float f1 = fir_state[(b * D3 + n3) * 2 + 1];
        const float* wr = sf_weight + n3 * 3;
        zp[j] = wr[2] * u + f0 * wr[0] + f1 * wr[1] + sf_bias[n3];
        out_fir[(b * D3 + n3) * 2 + 0] = f1;
        out_fir[(b * D3 + n3) * 2 + 1] = u;
    }
    g_x2 [b * Dm + d] = zp[0];
    g_x1v[b * Dm + d] = zp[1] * zp[2];
}

// ---------------- IIR: one thread per (d, s); exp once per (d,s) ----------------
__global__ void k_iir(const float* __restrict__ iir_state,
                      const float* __restrict__ D_res,
                      const float* __restrict__ residues,
                      const float* __restrict__ log_poles,
                      float* __restrict__ out_iir) {
    int idx = blockIdx.x * blockDim.x + threadIdx.x;   // [0, 65536)
    int d = idx >> 4;
    int s = idx & 15;

    float pole = __expf(log_poles[d * Ssz + s]);
    float r    = residues[d * Ssz + s];
    float dres = D_res[d];

#pragma unroll
    for (int b = 0; b < Bsz; b++) {
        float x1v = g_x1v[b * Dm + d];
        float ni  = pole * iir_state[(b * Dm + d) * Ssz + s] + x1v;
        out_iir[(b * Dm + d) * Ssz + s] = ni;
        float c = r * ni;
#pragma unroll
        for (int o = 1; o < 16; o <<= 1) c += __shfl_xor_sync(0xffffffffu, c, o);
        if (s == 0)
            g_y[b * Dm + d] = g_x2[b * Dm + d] * (c + dres * x1v);
    }
}

// ---------------- silu gate + seed final output with xout ----------------
__global__ void k_silu(float* __restrict__ out_x) {
    int i = blockIdx.x * blockDim.x + threadIdx.x;     // 131072 threads
    if (i < Bsz * FFm) {
        float a = g_g1[i];
        g_h[i] = (a / (1.f + __expf(-a))) * g_g3[i];
    }
    if (i < Bsz * Dm) out_x[i] = g_xout[i];
}

// ---------------- launcher ----------------
extern "C" void kernel_launch(void* const* d_in, const int* in_sizes, int n_in,
                              void* d_out, int out_size) {
    const float* x           = (const float*)d_in[0];
    const float* fir_state   = (const float*)d_in[1];
    const float* iir_state   = (const float*)d_in[2];
    const float* pre_norm_w  = (const float*)d_in[3];
    const float* proj_w      = (const float*)d_in[4];
    const float* sf_weight   = (const float*)d_in[5];
    const float* sf_bias     = (const float*)d_in[6];
    const float* D_res       = (const float*)d_in[7];
    const float* residues    = (const float*)d_in[8];
    const float* log_poles   = (const float*)d_in[9];
    const float* out_w       = (const float*)d_in[10];
    const float* out_b       = (const float*)d_in[11];
    const float* post_norm_w = (const float*)d_in[12];
    const float* mlp_w1      = (const float*)d_in[13];
    const float* mlp_w3      = (const float*)d_in[14];
    const float* mlp_w2      = (const float*)d_in[15];

    float* out_x   = (float*)d_out;                    // [8, 1, 4096]
    float* out_fir = out_x + Bsz * Dm;                 // [8, 12288, 2]
    float* out_iir = out_fir + Bsz * D3 * 2;           // [8, 4096, 16]

    k_init        <<<512, 256>>>(x, out_b);
    k_rmsnorm_pre <<<Bsz, 1024>>>(x, pre_norm_w);
    k_gemv_proj   <<<dim3(D3 / 1024, Dm / 128), 256>>>(proj_w);
    k_fir         <<<(Bsz * Dm) / 256, 256>>>(fir_state, sf_weight, sf_bias, out_fir);
    k_iir         <<<(Dm * Ssz) / 256, 256>>>(iir_state, D_res, residues, log_poles, out_iir);
    k_gemv_out    <<<dim3(Dm / 1024, Dm / 64), 256>>>(out_w);
    k_rmsnorm_post<<<Bsz, 1024>>>(post_norm_w);
    k_gemv_w1     <<<dim3(FFm / 1024, Dm / 128), 256>>>(mlp_w1);
    k_gemv_w3     <<<dim3(FFm / 1024, Dm / 128), 256>>>(mlp_w3);
    k_silu        <<<512, 256>>>(out_x);
    k_gemv_w2     <<<dim3(Dm / 1024, FFm / 128), 256>>>(mlp_w2, out_x);
}

// round 3
// speedup vs baseline: 1.6982x; 1.6982x over previous
#include <cuda_runtime.h>
#include <cuda_bf16.h>
#include <cstdint>

#define Bsz 8
#define Dm  4096
#define D3  12288
#define Ssz 16
#define FFm 16384

typedef unsigned long long u64;

// ---------------- scratch (allocation-free: __device__ globals) ----------------
__device__ float g_xn  [Bsz * Dm];
__device__ float g_z   [Bsz * D3];
__device__ float g_x2  [Bsz * Dm];
__device__ float g_x1v [Bsz * Dm];
__device__ float g_y   [Bsz * Dm];
__device__ float g_xout[Bsz * Dm];
__device__ float g_xn2 [Bsz * Dm];
__device__ float g_g1  [Bsz * FFm];
__device__ float g_g3  [Bsz * FFm];
__device__ float g_h   [Bsz * FFm];

// ---------------- packed f32x2 helpers ----------------
__device__ __forceinline__ u64 pack2(float lo, float hi) {
    u64 r;
    asm("mov.b64 %0, {%1, %2};" : "=l"(r) : "r"(__float_as_uint(lo)), "r"(__float_as_uint(hi)));
    return r;
}
__device__ __forceinline__ void unpack2(u64 v, float& lo, float& hi) {
    unsigned ulo, uhi;
    asm("mov.b64 {%0, %1}, %2;" : "=r"(ulo), "=r"(uhi) : "l"(v));
    lo = __uint_as_float(ulo); hi = __uint_as_float(uhi);
}

// ---------------- batched (B=8) split-K GEMV, software-pipelined ----------------
// W: [K, N] row-major. out[b,n] += sum_k xin[b,k]*W[k,n]
// 256 threads; thread owns 4 consecutive cols (LDG.128). Block covers 1024 cols.
// grid = (N/1024, K/KCHUNK). Mainloop: stage 8 float4 loads into regs (MLP=8),
// then FMA phase. x held in smem as duplicated (xb,xb) u64 pairs, read as LDS.128.
template<int KCHUNK>
__device__ __forceinline__ void gemv4_body(const float* __restrict__ W,
                                           const float* __restrict__ xin,
                                           float* __restrict__ out,
                                           int K, int N) {
    __shared__ __align__(16) u64 xs2[KCHUNK * 8];
    const int n0 = (blockIdx.x * 256 + threadIdx.x) * 4;
    const int k0 = blockIdx.y * KCHUNK;

    for (int t = threadIdx.x; t < KCHUNK * 8; t += 256) {
        int b = t / KCHUNK, k = t - b * KCHUNK;
        float v = xin[b * K + k0 + k];
        xs2[k * 8 + b] = pack2(v, v);
    }
    __syncthreads();

    u64 acc01[8], acc23[8];
#pragma unroll
    for (int b = 0; b < 8; b++) { acc01[b] = pack2(0.f, 0.f); acc23[b] = pack2(0.f, 0.f); }

    const float4* Wp = reinterpret_cast<const float4*>(W + (size_t)k0 * N + n0);
    const size_t strd = (size_t)(N >> 2);

    for (int kb = 0; kb < KCHUNK; kb += 8) {
        // ---- load phase: 8 independent LDG.128 in flight ----
        float4 w[8];
#pragma unroll
        for (int u = 0; u < 8; u++)
            w[u] = Wp[(size_t)(kb + u) * strd];

        // ---- compute phase ----
#pragma unroll
        for (int u = 0; u < 8; u++) {
            u64 w01 = pack2(w[u].x, w[u].y);
            u64 w23 = pack2(w[u].z, w[u].w);
            const ulonglong2* xp = reinterpret_cast<const ulonglong2*>(xs2 + (kb + u) * 8);
#pragma unroll
            for (int j = 0; j < 4; j++) {
                ulonglong2 xb2 = xp[j];
                asm("fma.rn.f32x2 %0, %1, %2, %0;" : "+l"(acc01[2*j  ]) : "l"(w01), "l"(xb2.x));
                asm("fma.rn.f32x2 %0, %1, %2, %0;" : "+l"(acc23[2*j  ]) : "l"(w23), "l"(xb2.x));
                asm("fma.rn.f32x2 %0, %1, %2, %0;" : "+l"(acc01[2*j+1]) : "l"(w01), "l"(xb2.y));
                asm("fma.rn.f32x2 %0, %1, %2, %0;" : "+l"(acc23[2*j+1]) : "l"(w23), "l"(xb2.y));
            }
        }
    }

#pragma unroll
    for (int b = 0; b < 8; b++) {
        float a0, a1, a2, a3;
        unpack2(acc01[b], a0, a1);
        unpack2(acc23[b], a2, a3);
        float* ob = out + (size_t)b * N + n0;
        atomicAdd(ob + 0, a0);
        atomicAdd(ob + 1, a1);
        atomicAdd(ob + 2, a2);
        atomicAdd(ob + 3, a3);
    }
}

__global__ void __launch_bounds__(256, 2) k_gemv_proj(const float* __restrict__ W) { gemv4_body<128>(W, g_xn,  g_z,    Dm,  D3);  }
__global__ void __launch_bounds__(256, 2) k_gemv_out (const float* __restrict__ W) { gemv4_body<64> (W, g_y,   g_xout, Dm,  Dm);  }
__global__ void __launch_bounds__(256, 2) k_gemv_w1  (const float* __restrict__ W) { gemv4_body<128>(W, g_xn2, g_g1,   Dm,  FFm); }
__global__ void __launch_bounds__(256, 2) k_gemv_w3  (const float* __restrict__ W) { gemv4_body<128>(W, g_xn2, g_g3,   Dm,  FFm); }
__global__ void __launch_bounds__(256, 2) k_gemv_w2  (const float* __restrict__ W, float* __restrict__ out_x) {
    gemv4_body<128>(W, g_h, out_x, FFm, Dm);
}

// ---------------- rmsnorm ----------------
__device__ __forceinline__ void rmsnorm_body(const float* __restrict__ xr,
                                             const float* __restrict__ w,
                                             float* __restrict__ xo) {
    float ss = 0.f;
    for (int i = threadIdx.x; i < Dm; i += blockDim.x) { float v = xr[i]; ss += v * v; }
#pragma unroll
    for (int o = 16; o; o >>= 1) ss += __shfl_xor_sync(0xffffffffu, ss, o);
    __shared__ float red[32];
    int wid = threadIdx.x >> 5, lane = threadIdx.x & 31;
    if (lane == 0) red[wid] = ss;
    __syncthreads();
    int nw = blockDim.x >> 5;
    if (wid == 0) {
        float t = (lane < nw) ? red[lane] : 0.f;
#pragma unroll
        for (int o = 16; o; o >>= 1) t += __shfl_xor_sync(0xffffffffu, t, o);
        if (lane == 0) red[0] = t;
    }
    __syncthreads();
    float scale = rsqrtf(red[0] * (1.f / Dm) + 1e-6f);
    for (int i = threadIdx.x; i < Dm; i += blockDim.x) xo[i] = xr[i] * scale * w[i];
}

__global__ void k_rmsnorm_pre(const float* __restrict__ x, const float* __restrict__ w) {
    int b = blockIdx.x;
    rmsnorm_body(x + b * Dm, w, g_xn + b * Dm);
}
__global__ void k_rmsnorm_post(const float* __restrict__ w) {
    int b = blockIdx.x;
    rmsnorm_body(g_xout + b * Dm, w, g_xn2 + b * Dm);
}

// ---------------- init ----------------
__global__ void k_init(const float* __restrict__ x, const float* __restrict__ out_b) {
    int i = blockIdx.x * blockDim.x + threadIdx.x;
    if (i < Bsz * D3)  g_z[i] = 0.f;
    if (i < Bsz * FFm) { g_g1[i] = 0.f; g_g3[i] = 0.f; }
    if (i < Bsz * Dm)  g_xout[i] = x[i] + out_b[i & (Dm - 1)];
}

// ---------------- FIR taps ----------------
__global__ void k_fir(const float* __restrict__ fir_state,
                      const float* __restrict__ sf_weight,
                      const float* __restrict__ sf_bias,
                      float* __restrict__ out_fir) {
    int idx = blockIdx.x * blockDim.x + threadIdx.x;
    int b = idx >> 12;
    int d = idx & (Dm - 1);
    int head = d >> 7;
    int i    = d & 127;
    int base = head * 384 + i;

    float zp[3];
#pragma unroll
    for (int j = 0; j < 3; j++) {
        int n3 = base + j * 128;
        float u  = g_z[b * D3 + n3];
        float f0 = fir_state[(b * D3 + n3) * 2 + 0];
        float f1 = fir_state[(b * D3 + n3) * 2 + 1];
        const float* wr = sf_weight + n3 * 3;
        zp[j] = wr[2] * u + f0 * wr[0] + f1 * wr[1] + sf_bias[n3];
        out_fir[(b * D3 + n3) * 2 + 0] = f1;
        out_fir[(b * D3 + n3) * 2 + 1] = u;
    }
    g_x2 [b * Dm + d] = zp[0];
    g_x1v[b * Dm + d] = zp[1] * zp[2];
}

// ---------------- IIR ----------------
__global__ void k_iir(const float* __restrict__ iir_state,
                      const float* __restrict__ D_res,
                      const float* __restrict__ residues,
                      const float* __restrict__ log_poles,
                      float* __restrict__ out_iir) {
    int idx = blockIdx.x * blockDim.x + threadIdx.x;
    int d = idx >> 4;
    int s = idx & 15;

    float pole = __expf(log_poles[d * Ssz + s]);
    float r    = residues[d * Ssz + s];
    float dres = D_res[d];

#pragma unroll
    for (int b = 0; b < Bsz; b++) {
        float x1v = g_x1v[b * Dm + d];
        float ni  = pole * iir_state[(b * Dm + d) * Ssz + s] + x1v;
        out_iir[(b * Dm + d) * Ssz + s] = ni;
        float c = r * ni;
#pragma unroll
        for (int o = 1; o < 16; o <<= 1) c += __shfl_xor_sync(0xffffffffu, c, o);
        if (s == 0)
            g_y[b * Dm + d] = g_x2[b * Dm + d] * (c + dres * x1v);
    }
}

// ---------------- silu gate + seed final output ----------------
__global__ void k_silu(float* __restrict__ out_x) {
    int i = blockIdx.x * blockDim.x + threadIdx.x;
    if (i < Bsz * FFm) {
        float a = g_g1[i];
        g_h[i] = (a / (1.f + __expf(-a))) * g_g3[i];
    }
    if (i < Bsz * Dm) out_x[i] = g_xout[i];
}

// ---------------- launcher ----------------
extern "C" void kernel_launch(void* const* d_in, const int* in_sizes, int n_in,
                              void* d_out, int out_size) {
    const float* x           = (const float*)d_in[0];
    const float* fir_state   = (const float*)d_in[1];
    const float* iir_state   = (const float*)d_in[2];
    const float* pre_norm_w  = (const float*)d_in[3];
    const float* proj_w      = (const float*)d_in[4];
    const float* sf_weight   = (const float*)d_in[5];
    const float* sf_bias     = (const float*)d_in[6];
    const float* D_res       = (const float*)d_in[7];
    const float* residues    = (const float*)d_in[8];
    const float* log_poles   = (const float*)d_in[9];
    const float* out_w       = (const float*)d_in[10];
    const float* out_b       = (const float*)d_in[11];
    const float* post_norm_w = (const float*)d_in[12];
    const float* mlp_w1      = (const float*)d_in[13];
    const float* mlp_w3      = (const float*)d_in[14];
    const float* mlp_w2      = (const float*)d_in[15];

    float* out_x   = (float*)d_out;                    // [8, 1, 4096]
    float* out_fir = out_x + Bsz * Dm;                 // [8, 12288, 2]
    float* out_iir = out_fir + Bsz * D3 * 2;           // [8, 4096, 16]

    k_init        <<<512, 256>>>(x, out_b);
    k_rmsnorm_pre <<<Bsz, 1024>>>(x, pre_norm_w);
    k_gemv_proj   <<<dim3(D3 / 1024, Dm / 128), 256>>>(proj_w);
    k_fir         <<<(Bsz * Dm) / 256, 256>>>(fir_state, sf_weight, sf_bias, out_fir);
    k_iir         <<<(Dm * Ssz) / 256, 256>>>(iir_state, D_res, residues, log_poles, out_iir);
    k_gemv_out    <<<dim3(Dm / 1024, Dm / 64), 256>>>(out_w);
    k_rmsnorm_post<<<Bsz, 1024>>>(post_norm_w);
    k_gemv_w1     <<<dim3(FFm / 1024, Dm / 128), 256>>>(mlp_w1);
    k_gemv_w3     <<<dim3(FFm / 1024, Dm / 128), 256>>>(mlp_w3);
    k_silu        <<<512, 256>>>(out_x);
    k_gemv_w2     <<<dim3(Dm / 1024, FFm / 128), 256>>>(mlp_w2, out_x);
}